// round 3
// baseline (speedup 1.0000x reference)
#include <cuda_runtime.h>
#include <math.h>

#define HH 64
#define WWD 192
#define HWX (HH*WWD)       // 12288
#define HP 66
#define WP 194
#define PP (HP*WP)         // 12804
#define CIN 256
#define CO 128
#define NBLK (HWX/32)      // 384 gemm row-blocks

// ---------------- scratch (device globals; no allocation) ----------------
__device__ float g_xT[PP*CIN];      // padded x, pixel-major (P, Cin)
__device__ int   g_idx[HWX*36];     // 9 taps x 4 indices
__device__ float g_wgt[HWX*36];     // 9 taps x 4 weights
__device__ float g_yT[HWX*CIN];     // gather output, pixel-major
__device__ float g_C1[HWX*CO];
__device__ float g_Z1[HWX*CO];
__device__ float g_C2[HWX*CO];
__device__ float g_Z2[HWX*CO];
__device__ float g_C3[HWX*CO];
__device__ float g_psum[NBLK*CO];
__device__ float g_psq[NBLK*CO];
__device__ float g_bn[3*2*CO];      // per stage: [scale(128), shift(128)]

// ---------------- 1) pad + transpose x: (Cin,H,W) -> (P, Cin) ----------------
__global__ void k_pad_transpose(const float* __restrict__ x) {
    __shared__ float s[32][33];
    int ptile = blockIdx.x * 32;
    int ctile = blockIdx.y * 32;
    int tx = threadIdx.x, ty = threadIdx.y;   // 32 x 8
    #pragma unroll
    for (int i = 0; i < 32; i += 8) {
        int c = ctile + ty + i;
        int p = ptile + tx;
        float v = 0.f;
        if (p < PP) {
            int ph = p / WP, pw = p % WP;
            if (ph >= 1 && ph <= HH && pw >= 1 && pw <= WWD)
                v = x[c*HWX + (ph-1)*WWD + (pw-1)];
        }
        s[ty+i][tx] = v;
    }
    __syncthreads();
    #pragma unroll
    for (int i = 0; i < 32; i += 8) {
        int p = ptile + ty + i;
        if (p < PP) g_xT[p*CIN + ctile + tx] = s[tx][ty+i];
    }
}

// ---------------- 2) per-pixel tap weights & indices ----------------
__global__ void k_weights(const float* __restrict__ x_range) {
    int p = blockIdx.x * blockDim.x + threadIdx.x;
    if (p >= HWX) return;
    int h = p / WWD, w = p % WWD;
    float off = 3.0f / (1.0f + expf(-x_range[p]));
    float v0 = (float)((h+1)*WP + (w+1));
    const float PM1 = (float)(PP - 1);
    #pragma unroll
    for (int t = 0; t < 9; t++) {
        float xo = (float)(t % 3 - 1);
        float yo = (float)(t / 3 - 1);
        float pre   = v0 + xo + yo*(float)WP;
        float ofv   = off*xo + yo*(float)WP;
        float after = pre + ofv;
        float avf  = fminf(fmaxf(pre + floorf(ofv), 0.f), PM1);
        float avf1 = fminf(fmaxf(avf + xo, 0.f), PM1);
        float avc  = fminf(fmaxf(pre + ceilf(ofv), 0.f), PM1);
        float avc1 = fminf(fmaxf(avc + xo, 0.f), PM1);
        float s1 = fabsf((after - avf)  / (float)WP);
        float s2 = fabsf((avc1 - after) / (float)WP);
        float w0 = s1 * fabsf(after - avf);   // vf
        float w1 = s1 * fabsf(avf1 - after);  // vf1
        float w2 = s2 * fabsf(after - avc1);  // vc1
        float w3 = s2 * fabsf(avc - after);   // vc
        int base = p*36 + t*4;
        g_idx[base+0] = (int)avf;
        g_idx[base+1] = (int)avf1;
        g_idx[base+2] = (int)avc1;
        g_idx[base+3] = (int)avc;
        g_wgt[base+0] = w0; g_wgt[base+1] = w1;
        g_wgt[base+2] = w2; g_wgt[base+3] = w3;
    }
}

// ---------------- 3) gather + tap-reduce -> yT (HW, Cin) ----------------
__global__ void k_gather(const float* __restrict__ range_out) {
    int p = blockIdx.x;       // 12288
    int c = threadIdx.x;      // 256
    __shared__ int   sidx[36];
    __shared__ float sw[36];
    if (c < 36) { sidx[c] = g_idx[p*36 + c]; sw[c] = g_wgt[p*36 + c]; }
    __syncthreads();
    float acc = 0.f;
    #pragma unroll
    for (int t = 0; t < 9; t++) {
        float w0 = sw[t*4+0], w1 = sw[t*4+1], w2 = sw[t*4+2], w3 = sw[t*4+3];
        // center-column taps have identically-zero weights away from clamps: skip loads
        if (w0 == 0.f && w1 == 0.f && w2 == 0.f && w3 == 0.f) continue;
        float v = w0 * g_xT[sidx[t*4+0]*CIN + c]
                + w1 * g_xT[sidx[t*4+1]*CIN + c]
                + w2 * g_xT[sidx[t*4+2]*CIN + c]
                + w3 * g_xT[sidx[t*4+3]*CIN + c];
        acc += range_out[c*9 + t] * v;
    }
    g_yT[p*CIN + c] = acc;
}

// ---------------- 4) NT GEMM  C[p][o] = sum_k A[p][k]*B[o][k], + BN partials ----------------
// M = 12288 (grid.x = 384, BM=32), N = 128, K in {256,128}
__global__ void k_gemm(const float* __restrict__ A, const float* __restrict__ B,
                       float* __restrict__ C, int K) {
    __shared__ float As[32][36];    // [k][m], 16B-aligned rows
    __shared__ float Bs[32][132];   // [k][n]
    __shared__ float reds[8][128];
    __shared__ float redq[8][128];
    int t  = threadIdx.x;          // 256
    int m0 = blockIdx.x * 32;
    int pg = t >> 5;               // 0..7  (pixel group)
    int og = t & 31;               // 0..31 (output group)
    float acc[4][4];
    #pragma unroll
    for (int i = 0; i < 4; i++)
        #pragma unroll
        for (int j = 0; j < 4; j++) acc[i][j] = 0.f;

    for (int k0 = 0; k0 < K; k0 += 32) {
        #pragma unroll
        for (int i = 0; i < 4; i++) {           // A tile 32x32
            int idx = t + i*256;
            int m = idx >> 5, k = idx & 31;
            As[k][m] = A[(m0+m)*K + k0 + k];
        }
        #pragma unroll
        for (int i = 0; i < 16; i++) {          // B tile 128x32
            int idx = t + i*256;
            int n = idx >> 5, k = idx & 31;
            Bs[k][n] = B[n*K + k0 + k];
        }
        __syncthreads();
        #pragma unroll
        for (int k = 0; k < 32; k++) {
            float4 a = *(const float4*)&As[k][pg*4];
            float4 b = *(const float4*)&Bs[k][og*4];
            acc[0][0] += a.x*b.x; acc[0][1] += a.x*b.y; acc[0][2] += a.x*b.z; acc[0][3] += a.x*b.w;
            acc[1][0] += a.y*b.x; acc[1][1] += a.y*b.y; acc[1][2] += a.y*b.z; acc[1][3] += a.y*b.w;
            acc[2][0] += a.z*b.x; acc[2][1] += a.z*b.y; acc[2][2] += a.z*b.z; acc[2][3] += a.z*b.w;
            acc[3][0] += a.w*b.x; acc[3][1] += a.w*b.y; acc[3][2] += a.w*b.z; acc[3][3] += a.w*b.w;
        }
        __syncthreads();
    }
    // write C + per-block BN partial sums (deterministic)
    float s[4], q[4];
    #pragma unroll
    for (int j = 0; j < 4; j++) { s[j] = 0.f; q[j] = 0.f; }
    #pragma unroll
    for (int i = 0; i < 4; i++) {
        float4 cv = make_float4(acc[i][0], acc[i][1], acc[i][2], acc[i][3]);
        *(float4*)&C[(m0 + pg*4 + i)*CO + og*4] = cv;
        #pragma unroll
        for (int j = 0; j < 4; j++) { s[j] += acc[i][j]; q[j] += acc[i][j]*acc[i][j]; }
    }
    #pragma unroll
    for (int j = 0; j < 4; j++) { reds[pg][og*4+j] = s[j]; redq[pg][og*4+j] = q[j]; }
    __syncthreads();
    if (t < 128) {
        float ts = 0.f, tq = 0.f;
        #pragma unroll
        for (int g = 0; g < 8; g++) { ts += reds[g][t]; tq += redq[g][t]; }
        g_psum[blockIdx.x*CO + t] = ts;
        g_psq [blockIdx.x*CO + t] = tq;
    }
}

// ---------------- 5) BN finalize ----------------
__global__ void k_bn_final(const float* __restrict__ gg, const float* __restrict__ bb, int stage) {
    int o = threadIdx.x;  // 128
    float s = 0.f, q = 0.f;
    for (int i = 0; i < NBLK; i++) { s += g_psum[i*CO + o]; q += g_psq[i*CO + o]; }
    float inv = 1.0f / (float)HWX;
    float mu  = s * inv;
    float var = q * inv - mu*mu;
    float sc  = gg[o] * rsqrtf(var + 1e-5f);
    g_bn[stage*2*CO + o]      = sc;
    g_bn[stage*2*CO + CO + o] = bb[o] - mu*sc;
}

// ---------------- 6) depthwise 3x3 on act(C) ----------------
__global__ void k_dw(const float* __restrict__ Cin_, const float* __restrict__ dww,
                     float* __restrict__ Z, int stage) {
    int p = blockIdx.x;           // 12288
    int c = threadIdx.x;          // 128
    int h = p / WWD, w = p % WWD;
    float sc = g_bn[stage*2*CO + c], sh = g_bn[stage*2*CO + CO + c];
    float acc = 0.f;
    #pragma unroll
    for (int t = 0; t < 9; t++) {
        int hh = h + t/3 - 1, ww = w + t%3 - 1;
        if (hh < 0 || hh >= HH || ww < 0 || ww >= WWD) continue;
        float v = Cin_[(hh*WWD + ww)*CO + c];
        float a = v*sc + sh;
        a = (a >= 0.f) ? a : 0.01f*a;
        acc += dww[c*9 + t] * a;
    }
    Z[p*CO + c] = acc;
}

// ---------------- 7) final act + transpose to NCHW ----------------
__global__ void k_final(float* __restrict__ out) {
    __shared__ float s[32][33];
    int ptile = blockIdx.x * 32;
    int ctile = blockIdx.y * 32;
    int tx = threadIdx.x, ty = threadIdx.y;  // 32 x 8
    #pragma unroll
    for (int i = 0; i < 32; i += 8) {
        int p = ptile + ty + i, c = ctile + tx;
        float v = g_C3[p*CO + c];
        float a = v*g_bn[2*2*CO + c] + g_bn[2*2*CO + CO + c];
        a = (a >= 0.f) ? a : 0.01f*a;
        s[ty+i][tx] = a;
    }
    __syncthreads();
    #pragma unroll
    for (int i = 0; i < 32; i += 8)
        out[(ctile + ty + i)*HWX + ptile + tx] = s[tx][ty+i];
}

// ---------------- launch ----------------
extern "C" void kernel_launch(void* const* d_in, const int* in_sizes, int n_in,
                              void* d_out, int out_size) {
    const float* x        = (const float*)d_in[0];
    const float* x_range  = (const float*)d_in[1];
    const float* range_o  = (const float*)d_in[2];
    const float* w_reduce = (const float*)d_in[3];
    const float* g_r      = (const float*)d_in[4];
    const float* b_r      = (const float*)d_in[5];
    const float* dw1      = (const float*)d_in[6];
    const float* pw1      = (const float*)d_in[7];
    const float* g1       = (const float*)d_in[8];
    const float* b1       = (const float*)d_in[9];
    const float* dw2      = (const float*)d_in[10];
    const float* pw2      = (const float*)d_in[11];
    const float* g2       = (const float*)d_in[12];
    const float* b2       = (const float*)d_in[13];
    float* out = (float*)d_out;

    float *yT, *C1, *Z1, *C2, *Z2, *C3;
    cudaGetSymbolAddress((void**)&yT, g_yT);
    cudaGetSymbolAddress((void**)&C1, g_C1);
    cudaGetSymbolAddress((void**)&Z1, g_Z1);
    cudaGetSymbolAddress((void**)&C2, g_C2);
    cudaGetSymbolAddress((void**)&Z2, g_Z2);
    cudaGetSymbolAddress((void**)&C3, g_C3);

    k_pad_transpose<<<dim3((PP+31)/32, CIN/32), dim3(32,8)>>>(x);
    k_weights<<<(HWX+255)/256, 256>>>(x_range);
    k_gather<<<HWX, CIN>>>(range_o);

    k_gemm<<<NBLK, 256>>>(yT, w_reduce, C1, CIN);
    k_bn_final<<<1, CO>>>(g_r, b_r, 0);
    k_dw<<<HWX, CO>>>(C1, dw1, Z1, 0);

    k_gemm<<<NBLK, 256>>>(Z1, pw1, C2, CO);
    k_bn_final<<<1, CO>>>(g1, b1, 1);
    k_dw<<<HWX, CO>>>(C2, dw2, Z2, 1);

    k_gemm<<<NBLK, 256>>>(Z2, pw2, C3, CO);
    k_bn_final<<<1, CO>>>(g2, b2, 2);

    k_final<<<dim3(HWX/32, CO/32), dim3(32,8)>>>(out);
}